// round 4
// baseline (speedup 1.0000x reference)
#include <cuda_runtime.h>
#include <math.h>

// Problem constants (GPT-2 small attention)
#define BB 4
#define SS 2048
#define HH 12
#define DD 64
#define HID 768
#define BH (BB * HH)                 // 48
#define N_OUT_O (BB * HH * SS * DD)  // 6,291,456

#define BT 128                       // block tile (scores: q and k; pv: q)
#define NT2 (SS / BT)                // 16 tiles per dim
#define NLT2 (NT2 * (NT2 + 1) / 2)   // 136 lower-triangle tiles
#define QP 129                       // padded transposed-tile stride (conflict-free)
#define VP 68                        // V tile stride (16B-aligned, conflict-free)

// Scratch: head-major Q (pre-scaled by 1/8), K, V. 3 * 25.2 MB.
__device__ float g_q[BH * SS * DD];
__device__ float g_k[BH * SS * DD];
__device__ float g_v[BH * SS * DD];

// ---------------------------------------------------------------------------
// Kernel 1: split heads + scale Q.  x: [B, S, 3*768] -> g_q/g_k/g_v [BH, S, 64]
// ---------------------------------------------------------------------------
__global__ void pack_qkv(const float* __restrict__ x) {
    int idx = blockIdx.x * blockDim.x + threadIdx.x;   // over B*S*192 float4s
    if (idx >= BB * SS * (HID / 4)) return;
    int c4 = idx % (HID / 4);                 // 0..191 (float4 within 768)
    int s  = (idx / (HID / 4)) % SS;
    int b  = idx / ((HID / 4) * SS);
    int h  = c4 >> 4;                         // /16
    int d4 = c4 & 15;

    const float4* xin = (const float4*)x + (size_t)(b * SS + s) * (3 * HID / 4);
    float4 q = xin[c4];
    float4 k = xin[c4 + 192];
    float4 v = xin[c4 + 384];
    q.x *= 0.125f; q.y *= 0.125f; q.z *= 0.125f; q.w *= 0.125f;

    size_t dst = ((size_t)(b * HH + h) * SS + s) * (DD / 4) + d4;
    ((float4*)g_q)[dst] = q;
    ((float4*)g_k)[dst] = k;
    ((float4*)g_v)[dst] = v;
}

// ---------------------------------------------------------------------------
// Kernel 2: scores = (Q/8) @ K^T for lower-triangle 128x128 tiles.
// grid = (136, 48), block = 256 (16x16 threads, 8x8 micro-tile each).
// d-loop: 2 chunks of 32, register-prefetch pipelined.
// ---------------------------------------------------------------------------
__global__ void __launch_bounds__(256, 2) scores_kernel(float* __restrict__ W) {
    __shared__ float Qs[32 * QP];   // [d][q] transposed, padded
    __shared__ float Ks[32 * QP];   // [d][k] transposed, padded

    int t  = blockIdx.x;
    int bh = blockIdx.y;
    int rt = (int)((sqrtf(8.0f * (float)t + 1.0f) - 1.0f) * 0.5f);
    while ((rt + 1) * (rt + 2) / 2 <= t) rt++;
    while (rt * (rt + 1) / 2 > t) rt--;
    int ct = t - rt * (rt + 1) / 2;

    int r0 = rt * BT, c0 = ct * BT;
    int tid = threadIdx.x;
    int tx = tid & 15, ty = tid >> 4;

    const float4* Qg = (const float4*)(g_q + (size_t)bh * SS * DD);
    const float4* Kg = (const float4*)(g_k + (size_t)bh * SS * DD);

    // Per-thread load pattern: 4 (row, d4) pairs per chunk.
    int lrow[4], ld4[4];
#pragma unroll
    for (int it = 0; it < 4; ++it) {
        int fi = it * 256 + tid;
        lrow[it] = fi >> 3;
        ld4[it]  = fi & 7;
    }

    float4 qpre[4], kpre[4];
    // Prefetch chunk 0.
#pragma unroll
    for (int it = 0; it < 4; ++it) {
        qpre[it] = Qg[(size_t)(r0 + lrow[it]) * 16 + ld4[it]];
        kpre[it] = Kg[(size_t)(c0 + lrow[it]) * 16 + ld4[it]];
    }

    float acc[8][8];
#pragma unroll
    for (int i = 0; i < 8; ++i)
#pragma unroll
        for (int j = 0; j < 8; ++j) acc[i][j] = 0.0f;

#pragma unroll 1
    for (int ch = 0; ch < 2; ++ch) {
#pragma unroll
        for (int it = 0; it < 4; ++it) {
            int row = lrow[it], d4 = ld4[it];
            Qs[(d4 * 4 + 0) * QP + row] = qpre[it].x;
            Qs[(d4 * 4 + 1) * QP + row] = qpre[it].y;
            Qs[(d4 * 4 + 2) * QP + row] = qpre[it].z;
            Qs[(d4 * 4 + 3) * QP + row] = qpre[it].w;
            Ks[(d4 * 4 + 0) * QP + row] = kpre[it].x;
            Ks[(d4 * 4 + 1) * QP + row] = kpre[it].y;
            Ks[(d4 * 4 + 2) * QP + row] = kpre[it].z;
            Ks[(d4 * 4 + 3) * QP + row] = kpre[it].w;
        }
        // Issue next-chunk global loads before the barrier: regs only, no smem
        // dependence, maximally early issue -> latency hidden under compute.
        if (ch == 0) {
#pragma unroll
            for (int it = 0; it < 4; ++it) {
                qpre[it] = Qg[(size_t)(r0 + lrow[it]) * 16 + 8 + ld4[it]];
                kpre[it] = Kg[(size_t)(c0 + lrow[it]) * 16 + 8 + ld4[it]];
            }
        }
        __syncthreads();

#pragma unroll 8
        for (int d = 0; d < 32; ++d) {
            float a[8], b[8];
#pragma unroll
            for (int i = 0; i < 8; ++i) a[i] = Qs[d * QP + ty + 16 * i];
#pragma unroll
            for (int j = 0; j < 8; ++j) b[j] = Ks[d * QP + tx + 16 * j];
#pragma unroll
            for (int i = 0; i < 8; ++i)
#pragma unroll
                for (int j = 0; j < 8; ++j) acc[i][j] += a[i] * b[j];
        }
        __syncthreads();
    }

    float* Wp = W + (size_t)bh * SS * SS;
#pragma unroll
    for (int i = 0; i < 8; ++i) {
        size_t rbase = (size_t)(r0 + ty + 16 * i) * SS + c0;
#pragma unroll
        for (int j = 0; j < 8; ++j) {
            Wp[rbase + tx + 16 * j] = acc[i][j];
        }
    }
}

// ---------------------------------------------------------------------------
// Kernel 3: in-place causal softmax per row (float4). grid = BH*S, block 512.
// One float4 per thread. Masked lanes get -1e30 sentinel -> expf -> exact 0.
// ---------------------------------------------------------------------------
__global__ void softmax_kernel(float* __restrict__ W) {
    __shared__ float redm[16];
    __shared__ float reds[16];
    int row = blockIdx.x;            // row = bh*S + q
    int q = row & (SS - 1);
    size_t base4 = (size_t)row * (SS / 4);
    float4* W4 = (float4*)W;
    int tid = threadIdx.x;
    int lane = tid & 31, wid = tid >> 5;

    int k0 = tid * 4;
    float4 v;
    if (k0 <= q) {
        v = W4[base4 + tid];
        if (k0 + 1 > q) v.y = -1e30f;
        if (k0 + 2 > q) v.z = -1e30f;
        if (k0 + 3 > q) v.w = -1e30f;
    } else {
        v = make_float4(-1e30f, -1e30f, -1e30f, -1e30f);
    }
    float mx = fmaxf(fmaxf(v.x, v.y), fmaxf(v.z, v.w));
#pragma unroll
    for (int o = 16; o > 0; o >>= 1) mx = fmaxf(mx, __shfl_xor_sync(0xffffffffu, mx, o));
    if (lane == 0) redm[wid] = mx;
    __syncthreads();
    mx = redm[0];
#pragma unroll
    for (int w = 1; w < 16; ++w) mx = fmaxf(mx, redm[w]);

    v.x = __expf(v.x - mx);
    v.y = __expf(v.y - mx);
    v.z = __expf(v.z - mx);
    v.w = __expf(v.w - mx);
    float sum = (v.x + v.y) + (v.z + v.w);
#pragma unroll
    for (int o = 16; o > 0; o >>= 1) sum += __shfl_xor_sync(0xffffffffu, sum, o);
    if (lane == 0) reds[wid] = sum;
    __syncthreads();
    sum = reds[0];
#pragma unroll
    for (int w = 1; w < 16; ++w) sum += reds[w];
    float inv = 1.0f / sum;

    v.x *= inv; v.y *= inv; v.z *= inv; v.w *= inv;
    W4[base4 + tid] = v;
}

// ---------------------------------------------------------------------------
// Kernel 4: attn_output = P @ V (causal). Tile 128(q) x 64(d), 8x4 micro.
// grid = (16, 48), block = 256. k in chunks of 32, register-prefetch pipelined.
// ---------------------------------------------------------------------------
__global__ void __launch_bounds__(256, 2) pv_kernel(const float* __restrict__ W,
                                                    float* __restrict__ O) {
    __shared__ float Ps[32 * QP];   // [k][q] transposed, padded
    __shared__ float Vs[32 * VP];   // [k][d] natural, padded

    int bt = blockIdx.x;
    int bh = blockIdx.y;
    int r0 = bt * BT;
    int tid = threadIdx.x;
    int tx = tid & 15, ty = tid >> 4;

    const float4* Wp4 = (const float4*)(W + (size_t)bh * SS * SS);
    const float4* Vg = (const float4*)(g_v + (size_t)bh * SS * DD);

    // Per-thread load pattern.
    int prow[4], pc4[4];
#pragma unroll
    for (int it = 0; it < 4; ++it) {
        int fi = it * 256 + tid;
        prow[it] = fi >> 3;
        pc4[it]  = fi & 7;
    }
    int vk[2], vd4[2];
#pragma unroll
    for (int it = 0; it < 2; ++it) {
        int fi = it * 256 + tid;
        vk[it]  = fi >> 4;
        vd4[it] = fi & 15;
    }

    float acc[8][4];
#pragma unroll
    for (int i = 0; i < 8; ++i)
#pragma unroll
        for (int j = 0; j < 4; ++j) acc[i][j] = 0.0f;

    int nch = (r0 + BT) >> 5;        // causal: chunks of 32 up to row-tile end

    float4 ppre[4], vpre[2];
    // Prefetch chunk 0.
#pragma unroll
    for (int it = 0; it < 4; ++it)
        ppre[it] = Wp4[(size_t)(r0 + prow[it]) * (SS / 4) + pc4[it]];
#pragma unroll
    for (int it = 0; it < 2; ++it)
        vpre[it] = Vg[(size_t)vk[it] * 16 + vd4[it]];

    for (int ch = 0; ch < nch; ++ch) {
#pragma unroll
        for (int it = 0; it < 4; ++it) {
            int row = prow[it], c4 = pc4[it];
            Ps[(c4 * 4 + 0) * QP + row] = ppre[it].x;
            Ps[(c4 * 4 + 1) * QP + row] = ppre[it].y;
            Ps[(c4 * 4 + 2) * QP + row] = ppre[it].z;
            Ps[(c4 * 4 + 3) * QP + row] = ppre[it].w;
        }
#pragma unroll
        for (int it = 0; it < 2; ++it) {
            *(float4*)(Vs + vk[it] * VP + vd4[it] * 4) = vpre[it];
        }
        // Issue next-chunk global loads before the barrier (regs only).
        if (ch + 1 < nch) {
            int k0n = (ch + 1) * 32;
#pragma unroll
            for (int it = 0; it < 4; ++it)
                ppre[it] = Wp4[(size_t)(r0 + prow[it]) * (SS / 4) + (k0n >> 2) + pc4[it]];
#pragma unroll
            for (int it = 0; it < 2; ++it)
                vpre[it] = Vg[(size_t)(k0n + vk[it]) * 16 + vd4[it]];
        }
        __syncthreads();

#pragma unroll 8
        for (int k = 0; k < 32; ++k) {
            float a[8], b[4];
#pragma unroll
            for (int i = 0; i < 8; ++i) a[i] = Ps[k * QP + ty + 16 * i];
#pragma unroll
            for (int j = 0; j < 4; ++j) b[j] = Vs[k * VP + tx + 16 * j];
#pragma unroll
            for (int i = 0; i < 8; ++i)
#pragma unroll
                for (int j = 0; j < 4; ++j) acc[i][j] += a[i] * b[j];
        }
        __syncthreads();
    }

    float* Op = O + (size_t)bh * SS * DD;
#pragma unroll
    for (int i = 0; i < 8; ++i) {
        size_t rbase = (size_t)(r0 + ty + 16 * i) * DD;
#pragma unroll
        for (int j = 0; j < 4; ++j) {
            Op[rbase + tx + 16 * j] = acc[i][j];
        }
    }
}

// ---------------------------------------------------------------------------
extern "C" void kernel_launch(void* const* d_in, const int* in_sizes, int n_in,
                              void* d_out, int out_size) {
    const float* x = (const float*)d_in[0];
    float* out_o = (float*)d_out;            // [B,H,S,D]
    float* out_w = out_o + N_OUT_O;          // [B,H,S,S]

    pack_qkv<<<(BB * SS * (HID / 4) + 255) / 256, 256>>>(x);

    dim3 gs(NLT2, BH);
    scores_kernel<<<gs, 256>>>(out_w);

    softmax_kernel<<<BH * SS, 512>>>(out_w);

    dim3 gp(NT2, BH);
    pv_kernel<<<gp, 256>>>(out_w, out_o);
}

// round 9
// speedup vs baseline: 1.7299x; 1.7299x over previous
#include <cuda_runtime.h>
#include <math.h>
#include <stdint.h>

// Problem constants (GPT-2 small attention)
#define BB 4
#define SS 2048
#define HH 12
#define DD 64
#define HID 768
#define BH (BB * HH)                 // 48
#define N_OUT_O (BB * HH * SS * DD)  // 6,291,456

#define BT 128                       // block tile (scores: q,k; pv: q)
#define NT2 (SS / BT)                // 16
#define NLT2 (NT2 * (NT2 + 1) / 2)   // 136 lower-triangle tiles

#define QSP 36   // stride for [row][k] tiles: frag bank = 4*g + t4 -> conflict-free
#define VSP 72   // stride for Vs [k][d]:      frag bank = 8*t4 + g -> conflict-free

// Scratch: head-major Q (pre-scaled by 1/8, tf32-rounded), K, V (tf32-rounded).
__device__ float g_q[BH * SS * DD];
__device__ float g_k[BH * SS * DD];
__device__ float g_v[BH * SS * DD];

__device__ __forceinline__ float to_tf32(float x) {
    float y;
    asm("cvt.rna.tf32.f32 %0, %1;" : "=f"(y) : "f"(x));
    return y;
}

// D = A(16x8, row) * B(8x8, col) + D, tf32 inputs (pre-rounded), fp32 accum.
__device__ __forceinline__ void mma_tf32(float* c, const uint32_t* a, const uint32_t* b) {
    asm volatile(
        "mma.sync.aligned.m16n8k8.row.col.f32.tf32.tf32.f32 "
        "{%0,%1,%2,%3}, {%4,%5,%6,%7}, {%8,%9}, {%0,%1,%2,%3};\n"
        : "+f"(c[0]), "+f"(c[1]), "+f"(c[2]), "+f"(c[3])
        : "r"(a[0]), "r"(a[1]), "r"(a[2]), "r"(a[3]), "r"(b[0]), "r"(b[1]));
}

// ---------------------------------------------------------------------------
// Kernel 1: split heads + scale Q + tf32-round. x:[B,S,2304] -> g_q/g_k/g_v
// ---------------------------------------------------------------------------
__global__ void pack_qkv(const float* __restrict__ x) {
    int idx = blockIdx.x * blockDim.x + threadIdx.x;   // over B*S*192 float4s
    if (idx >= BB * SS * (HID / 4)) return;
    int c4 = idx % (HID / 4);
    int s  = (idx / (HID / 4)) % SS;
    int b  = idx / ((HID / 4) * SS);
    int h  = c4 >> 4;
    int d4 = c4 & 15;

    const float4* xin = (const float4*)x + (size_t)(b * SS + s) * (3 * HID / 4);
    float4 q = xin[c4];
    float4 k = xin[c4 + 192];
    float4 v = xin[c4 + 384];
    q.x = to_tf32(q.x * 0.125f); q.y = to_tf32(q.y * 0.125f);
    q.z = to_tf32(q.z * 0.125f); q.w = to_tf32(q.w * 0.125f);
    k.x = to_tf32(k.x); k.y = to_tf32(k.y); k.z = to_tf32(k.z); k.w = to_tf32(k.w);
    v.x = to_tf32(v.x); v.y = to_tf32(v.y); v.z = to_tf32(v.z); v.w = to_tf32(v.w);

    size_t dst = ((size_t)(b * HH + h) * SS + s) * (DD / 4) + d4;
    ((float4*)g_q)[dst] = q;
    ((float4*)g_k)[dst] = k;
    ((float4*)g_v)[dst] = v;
}

// ---------------------------------------------------------------------------
// Kernel 2: scores = (Q/8) @ K^T, lower-triangle 128x128 tiles, TF32 mma.
// grid = (136, 48), block = 256 (8 warps in 2x4; warp tile 64x32).
// ---------------------------------------------------------------------------
__global__ void __launch_bounds__(256) scores_kernel(float* __restrict__ W) {
    __shared__ __align__(16) float Qs[BT * QSP];  // [q][d-chunk 32]
    __shared__ __align__(16) float Ks[BT * QSP];  // [k][d-chunk 32]

    int t  = blockIdx.x;
    int bh = blockIdx.y;
    int rt = (int)((sqrtf(8.0f * (float)t + 1.0f) - 1.0f) * 0.5f);
    while ((rt + 1) * (rt + 2) / 2 <= t) rt++;
    while (rt * (rt + 1) / 2 > t) rt--;
    int ct = t - rt * (rt + 1) / 2;

    int r0 = rt * BT, c0 = ct * BT;
    int tid = threadIdx.x;
    int wid = tid >> 5, lane = tid & 31;
    int wm = wid >> 2, wn = wid & 3;      // warp grid 2(m) x 4(n)
    int g = lane >> 2, t4 = lane & 3;     // fragment coords

    const float4* Qg = (const float4*)(g_q + (size_t)bh * SS * DD);
    const float4* Kg = (const float4*)(g_k + (size_t)bh * SS * DD);

    float acc[4][4][4];
#pragma unroll
    for (int mt = 0; mt < 4; ++mt)
#pragma unroll
        for (int nt = 0; nt < 4; ++nt)
#pragma unroll
            for (int e = 0; e < 4; ++e) acc[mt][nt][e] = 0.0f;

#pragma unroll 1
    for (int ch = 0; ch < 2; ++ch) {
        float4 qv[4], kv[4];
#pragma unroll
        for (int it = 0; it < 4; ++it) {
            int fi = it * 256 + tid;
            int row = fi >> 3, d4 = fi & 7;
            qv[it] = Qg[(size_t)(r0 + row) * 16 + ch * 8 + d4];
            kv[it] = Kg[(size_t)(c0 + row) * 16 + ch * 8 + d4];
        }
        if (ch) __syncthreads();          // all warps done reading prev chunk
#pragma unroll
        for (int it = 0; it < 4; ++it) {
            int fi = it * 256 + tid;
            int row = fi >> 3, d4 = fi & 7;
            *(float4*)(Qs + row * QSP + d4 * 4) = qv[it];
            *(float4*)(Ks + row * QSP + d4 * 4) = kv[it];
        }
        __syncthreads();

#pragma unroll
        for (int ks = 0; ks < 4; ++ks) {
            int k0 = ks * 8;
            uint32_t a[4][4], b[4][2];
#pragma unroll
            for (int mt = 0; mt < 4; ++mt) {
                int rb = wm * 64 + mt * 16 + g;
                a[mt][0] = __float_as_uint(Qs[rb * QSP + k0 + t4]);
                a[mt][1] = __float_as_uint(Qs[(rb + 8) * QSP + k0 + t4]);
                a[mt][2] = __float_as_uint(Qs[rb * QSP + k0 + t4 + 4]);
                a[mt][3] = __float_as_uint(Qs[(rb + 8) * QSP + k0 + t4 + 4]);
            }
#pragma unroll
            for (int nt = 0; nt < 4; ++nt) {
                int cb = wn * 32 + nt * 8 + g;
                b[nt][0] = __float_as_uint(Ks[cb * QSP + k0 + t4]);
                b[nt][1] = __float_as_uint(Ks[cb * QSP + k0 + t4 + 4]);
            }
#pragma unroll
            for (int mt = 0; mt < 4; ++mt)
#pragma unroll
                for (int nt = 0; nt < 4; ++nt)
                    mma_tf32(acc[mt][nt], a[mt], b[nt]);
        }
    }

    float* Wp = W + (size_t)bh * SS * SS;
#pragma unroll
    for (int mt = 0; mt < 4; ++mt) {
        int r = r0 + wm * 64 + mt * 16 + g;
#pragma unroll
        for (int nt = 0; nt < 4; ++nt) {
            int c = c0 + wn * 32 + nt * 8 + 2 * t4;
            *(float2*)(Wp + (size_t)r * SS + c) =
                make_float2(acc[mt][nt][0], acc[mt][nt][1]);
            *(float2*)(Wp + (size_t)(r + 8) * SS + c) =
                make_float2(acc[mt][nt][2], acc[mt][nt][3]);
        }
    }
}

// ---------------------------------------------------------------------------
// Kernel 3: in-place causal softmax per row; output tf32-rounded (P operand
// for pv + final weights). grid = BH*S, block 512, one float4/thread.
// ---------------------------------------------------------------------------
__global__ void softmax_kernel(float* __restrict__ W) {
    __shared__ float redm[16];
    __shared__ float reds[16];
    int row = blockIdx.x;
    int q = row & (SS - 1);
    size_t base4 = (size_t)row * (SS / 4);
    float4* W4 = (float4*)W;
    int tid = threadIdx.x;
    int lane = tid & 31, wid = tid >> 5;

    int k0 = tid * 4;
    float4 v;
    if (k0 <= q) {
        v = W4[base4 + tid];
        if (k0 + 1 > q) v.y = -1e30f;
        if (k0 + 2 > q) v.z = -1e30f;
        if (k0 + 3 > q) v.w = -1e30f;
    } else {
        v = make_float4(-1e30f, -1e30f, -1e30f, -1e30f);
    }
    float mx = fmaxf(fmaxf(v.x, v.y), fmaxf(v.z, v.w));
#pragma unroll
    for (int o = 16; o > 0; o >>= 1) mx = fmaxf(mx, __shfl_xor_sync(0xffffffffu, mx, o));
    if (lane == 0) redm[wid] = mx;
    __syncthreads();
    mx = redm[0];
#pragma unroll
    for (int w = 1; w < 16; ++w) mx = fmaxf(mx, redm[w]);

    v.x = __expf(v.x - mx);
    v.y = __expf(v.y - mx);
    v.z = __expf(v.z - mx);
    v.w = __expf(v.w - mx);
    float sum = (v.x + v.y) + (v.z + v.w);
#pragma unroll
    for (int o = 16; o > 0; o >>= 1) sum += __shfl_xor_sync(0xffffffffu, sum, o);
    if (lane == 0) reds[wid] = sum;
    __syncthreads();
    sum = reds[0];
#pragma unroll
    for (int w = 1; w < 16; ++w) sum += reds[w];
    float inv = 1.0f / sum;

    v.x = to_tf32(v.x * inv);
    v.y = to_tf32(v.y * inv);
    v.z = to_tf32(v.z * inv);
    v.w = to_tf32(v.w * inv);
    W4[base4 + tid] = v;
}

// ---------------------------------------------------------------------------
// Kernel 4: attn_output = P @ V (causal), TF32 mma. Tile 128(q) x 64(d).
// grid = (16, 48), block 256 (8 warps in 2x4; warp tile 64x16).
// ---------------------------------------------------------------------------
__global__ void __launch_bounds__(256, 2) pv_kernel(const float* __restrict__ W,
                                                    float* __restrict__ O) {
    __shared__ __align__(16) float Ps[BT * QSP];  // [q][k-chunk 32]
    __shared__ __align__(16) float Vs[32 * VSP];  // [k][d]

    int bt = blockIdx.x;
    int bh = blockIdx.y;
    int r0 = bt * BT;
    int tid = threadIdx.x;
    int wid = tid >> 5, lane = tid & 31;
    int wm = wid >> 2, wn = wid & 3;
    int g = lane >> 2, t4 = lane & 3;

    const float4* Wp4 = (const float4*)(W + (size_t)bh * SS * SS);
    const float4* Vg = (const float4*)(g_v + (size_t)bh * SS * DD);

    int prow[4], pc4[4];
#pragma unroll
    for (int it = 0; it < 4; ++it) {
        int fi = it * 256 + tid;
        prow[it] = fi >> 3;
        pc4[it]  = fi & 7;
    }
    int vk[2], vd4[2];
#pragma unroll
    for (int it = 0; it < 2; ++it) {
        int fi = it * 256 + tid;
        vk[it]  = fi >> 4;
        vd4[it] = fi & 15;
    }

    float acc[4][2][4];
#pragma unroll
    for (int mt = 0; mt < 4; ++mt)
#pragma unroll
        for (int nt = 0; nt < 2; ++nt)
#pragma unroll
            for (int e = 0; e < 4; ++e) acc[mt][nt][e] = 0.0f;

    int nch = (r0 + BT) >> 5;

    float4 ppre[4], vpre[2];
#pragma unroll
    for (int it = 0; it < 4; ++it)
        ppre[it] = Wp4[(size_t)(r0 + prow[it]) * (SS / 4) + pc4[it]];
#pragma unroll
    for (int it = 0; it < 2; ++it)
        vpre[it] = Vg[(size_t)vk[it] * 16 + vd4[it]];

    for (int ch = 0; ch < nch; ++ch) {
        if (ch) __syncthreads();          // all warps done reading prev chunk
#pragma unroll
        for (int it = 0; it < 4; ++it)
            *(float4*)(Ps + prow[it] * QSP + pc4[it] * 4) = ppre[it];
#pragma unroll
        for (int it = 0; it < 2; ++it)
            *(float4*)(Vs + vk[it] * VSP + vd4[it] * 4) = vpre[it];

        if (ch + 1 < nch) {               // prefetch next chunk (regs only)
            int k0n = (ch + 1) * 32;
#pragma unroll
            for (int it = 0; it < 4; ++it)
                ppre[it] = Wp4[(size_t)(r0 + prow[it]) * (SS / 4) + (k0n >> 2) + pc4[it]];
#pragma unroll
            for (int it = 0; it < 2; ++it)
                vpre[it] = Vg[(size_t)(k0n + vk[it]) * 16 + vd4[it]];
        }
        __syncthreads();

#pragma unroll
        for (int ks = 0; ks < 4; ++ks) {
            int k0 = ks * 8;
            uint32_t a[4][4], b[2][2];
#pragma unroll
            for (int mt = 0; mt < 4; ++mt) {
                int rb = wm * 64 + mt * 16 + g;
                a[mt][0] = __float_as_uint(Ps[rb * QSP + k0 + t4]);
                a[mt][1] = __float_as_uint(Ps[(rb + 8) * QSP + k0 + t4]);
                a[mt][2] = __float_as_uint(Ps[rb * QSP + k0 + t4 + 4]);
                a[mt][3] = __float_as_uint(Ps[(rb + 8) * QSP + k0 + t4 + 4]);
            }
#pragma unroll
            for (int nt = 0; nt < 2; ++nt) {
                int cb = wn * 16 + nt * 8 + g;
                b[nt][0] = __float_as_uint(Vs[(k0 + t4) * VSP + cb]);
                b[nt][1] = __float_as_uint(Vs[(k0 + t4 + 4) * VSP + cb]);
            }
#pragma unroll
            for (int mt = 0; mt < 4; ++mt)
#pragma unroll
                for (int nt = 0; nt < 2; ++nt)
                    mma_tf32(acc[mt][nt], a[mt], b[nt]);
        }
    }

    float* Op = O + (size_t)bh * SS * DD;
#pragma unroll
    for (int mt = 0; mt < 4; ++mt) {
        int r = r0 + wm * 64 + mt * 16 + g;
#pragma unroll
        for (int nt = 0; nt < 2; ++nt) {
            int c = wn * 16 + nt * 8 + 2 * t4;
            *(float2*)(Op + (size_t)r * DD + c) =
                make_float2(acc[mt][nt][0], acc[mt][nt][1]);
            *(float2*)(Op + (size_t)(r + 8) * DD + c) =
                make_float2(acc[mt][nt][2], acc[mt][nt][3]);
        }
    }
}

// ---------------------------------------------------------------------------
extern "C" void kernel_launch(void* const* d_in, const int* in_sizes, int n_in,
                              void* d_out, int out_size) {
    const float* x = (const float*)d_in[0];
    float* out_o = (float*)d_out;            // [B,H,S,D]
    float* out_w = out_o + N_OUT_O;          // [B,H,S,S]

    pack_qkv<<<(BB * SS * (HID / 4) + 255) / 256, 256>>>(x);

    dim3 gs(NLT2, BH);
    scores_kernel<<<gs, 256>>>(out_w);

    softmax_kernel<<<BH * SS, 512>>>(out_w);

    dim3 gp(NT2, BH);
    pv_kernel<<<gp, 256>>>(out_w, out_o);
}